// round 4
// baseline (speedup 1.0000x reference)
#include <cuda_runtime.h>
#include <math.h>

// Problem constants
#define N_NODES 20000
#define N_EDGES 320000
#define EE_TOT  (N_EDGES + N_NODES)   // with self loops
#define FDIM    64
#define NHEAD   4
#define HF      256                   // NHEAD * FDIM
#define NGR     64
#define LATD    512
#define GCOLS   832                   // FDIM * (1 + 3*NHEAD)

// -------- scratch (static device globals; no allocation allowed) --------
static __device__ __align__(16) float d_n0 [N_NODES * FDIM];
static __device__ __align__(16) float d_x  [N_NODES * HF];
static __device__ __align__(16) float d_h  [N_NODES * HF];
static __device__ __align__(16) float d_acc[N_NODES * HF];
static __device__ __align__(16) float d_s  [N_NODES * NHEAD];
static __device__ __align__(16) float d_dt [N_NODES * NHEAD];
static __device__ __align__(16) float d_m  [N_NODES * NHEAD];
static __device__ __align__(16) float d_den[N_NODES * NHEAD];
static __device__ __align__(16) float d_e  [EE_TOT * NHEAD];
static __device__ __align__(16) float d_g  [NGR * GCOLS];
static __device__ __align__(16) float d_lat[NGR * LATD];

__device__ __forceinline__ float lrelu(float x) { return x > 0.f ? x : 0.2f * x; }

// float atomic max handling negative values (init must be -inf)
__device__ __forceinline__ void atomicMaxF(float* a, float v) {
    if (v >= 0.f) atomicMax((int*)a, __float_as_int(v));
    else          atomicMin((unsigned int*)a, __float_as_uint(v));
}

__device__ __forceinline__ void red_add_f4(float* addr, float x, float y, float z, float w) {
    asm volatile("red.global.add.v4.f32 [%0], {%1,%2,%3,%4};"
                 :: "l"(addr), "f"(x), "f"(y), "f"(z), "f"(w) : "memory");
}

// ---------------- zero the pooled-feature buffer ----------------
__global__ void zero_g_kernel() {
    int i = blockIdx.x * blockDim.x + threadIdx.x;
    if (i < NGR * GCOLS) d_g[i] = 0.f;
}

// ---------------- node feature encoders + mask mix + pool n0 ----------------
// 16 nodes per block, 256 threads. street_W kept in shared (transposed, padded).
__global__ void node_init_kernel(const float* __restrict__ sfeat,
                                 const float* __restrict__ bfeat,
                                 const float* __restrict__ smask,
                                 const float* __restrict__ bmask,
                                 const float* __restrict__ sW,
                                 const float* __restrict__ sb,
                                 const float* __restrict__ bW,
                                 const float* __restrict__ bb,
                                 const int*   __restrict__ batch)
{
    __shared__ float sWs[128 * 65];   // [k][f], padded stride 65
    __shared__ float xs[4 * 128];
    int tid = threadIdx.x;
    for (int li = tid; li < 64 * 128; li += 256) {
        int f = li >> 7;
        int k = li & 127;
        sWs[k * 65 + f] = sW[li];     // sW row-major [64,128]
    }
    __syncthreads();

    int nb0 = blockIdx.x * 16;
    for (int grp = 0; grp < 4; grp++) {
        int nb = nb0 + grp * 4;
        xs[tid]       = sfeat[nb * 128 + tid];
        xs[tid + 256] = sfeat[nb * 128 + tid + 256];
        __syncthreads();
        int ni = tid >> 6;
        int f  = tid & 63;
        int n  = nb + ni;
        float acc = sb[f];
        #pragma unroll 8
        for (int k = 0; k < 128; k++)
            acc = fmaf(xs[ni * 128 + k], sWs[k * 65 + f], acc);
        float sv = fmaxf(acc, 0.f);
        float bacc = bb[f];
        #pragma unroll
        for (int k = 0; k < 5; k++)
            bacc = fmaf(bfeat[n * 5 + k], bW[f * 5 + k], bacc);
        float bv = fmaxf(bacc, 0.f);
        float v = sv * smask[n] + bv * bmask[n];
        d_n0[n * FDIM + f] = v;
        atomicMax((int*)&d_g[batch[n] * GCOLS + f], __float_as_int(v));  // v >= 0
        __syncthreads();
    }
}

// ---------------- generic tiled SGEMM: C[M,N] = A[M,K] @ B[N,K]^T (+bias) ----------------
template<int BM, int BN, int BK, int TM, int TN, int NT>
__global__ void sgemm_tn(const float* __restrict__ A, const float* __restrict__ B,
                         const float* __restrict__ bias, float* __restrict__ C,
                         int M, int N, int K)
{
    __shared__ float As[BK][BM];
    __shared__ float Bs[BK][BN];
    int tid = threadIdx.x;
    int tx = tid % (BN / TN);
    int ty = tid / (BN / TN);
    int m0 = blockIdx.x * BM;
    int n0 = blockIdx.y * BN;

    float acc[TM][TN];
    #pragma unroll
    for (int i = 0; i < TM; i++)
        #pragma unroll
        for (int j = 0; j < TN; j++) acc[i][j] = 0.f;

    for (int k0 = 0; k0 < K; k0 += BK) {
        for (int li = tid; li < BM * BK / 4; li += NT) {
            int r  = li / (BK / 4);
            int c4 = li % (BK / 4);
            float4 v = make_float4(0.f, 0.f, 0.f, 0.f);
            if (m0 + r < M)
                v = *(const float4*)&A[(size_t)(m0 + r) * K + k0 + c4 * 4];
            As[c4 * 4 + 0][r] = v.x;
            As[c4 * 4 + 1][r] = v.y;
            As[c4 * 4 + 2][r] = v.z;
            As[c4 * 4 + 3][r] = v.w;
        }
        for (int li = tid; li < BN * BK / 4; li += NT) {
            int r  = li / (BK / 4);
            int c4 = li % (BK / 4);
            float4 v = *(const float4*)&B[(size_t)(n0 + r) * K + k0 + c4 * 4];
            Bs[c4 * 4 + 0][r] = v.x;
            Bs[c4 * 4 + 1][r] = v.y;
            Bs[c4 * 4 + 2][r] = v.z;
            Bs[c4 * 4 + 3][r] = v.w;
        }
        __syncthreads();
        #pragma unroll
        for (int k = 0; k < BK; k++) {
            float a[TM], b[TN];
            #pragma unroll
            for (int i = 0; i < TM; i++) a[i] = As[k][ty * TM + i];
            #pragma unroll
            for (int j = 0; j < TN; j++) b[j] = Bs[k][tx * TN + j];
            #pragma unroll
            for (int i = 0; i < TM; i++)
                #pragma unroll
                for (int j = 0; j < TN; j++)
                    acc[i][j] = fmaf(a[i], b[j], acc[i][j]);
        }
        __syncthreads();
    }

    #pragma unroll
    for (int i = 0; i < TM; i++) {
        int row = m0 + ty * TM + i;
        if (row >= M) continue;
        #pragma unroll
        for (int j = 0; j < TN; j++) {
            int col = n0 + tx * TN + j;
            float v = acc[i][j];
            if (bias) v += bias[col];
            C[(size_t)row * N + col] = v;
        }
    }
}

// ---------------- per-node attention scores s,d (warp per node) ----------------
__global__ void attn_scores_kernel(const float* __restrict__ h,
                                   const float* __restrict__ asrc,
                                   const float* __restrict__ adst)
{
    int w = (blockIdx.x * blockDim.x + threadIdx.x) >> 5;
    if (w >= N_NODES) return;
    int lane = threadIdx.x & 31;
    const float* hp = h + (size_t)w * HF;
    #pragma unroll
    for (int hh = 0; hh < NHEAD; hh++) {
        float x1 = hp[hh * 64 + lane];
        float x2 = hp[hh * 64 + lane + 32];
        float ps = x1 * asrc[hh * 64 + lane] + x2 * asrc[hh * 64 + lane + 32];
        float pd = x1 * adst[hh * 64 + lane] + x2 * adst[hh * 64 + lane + 32];
        #pragma unroll
        for (int o = 16; o > 0; o >>= 1) {
            ps += __shfl_down_sync(0xFFFFFFFFu, ps, o);
            pd += __shfl_down_sync(0xFFFFFFFFu, pd, o);
        }
        if (lane == 0) { d_s[w * NHEAD + hh] = ps; d_dt[w * NHEAD + hh] = pd; }
    }
}

// ---------------- per-layer init: acc=0, m=-inf, den=0 ----------------
__global__ void init_layer_kernel() {
    int i = blockIdx.x * blockDim.x + threadIdx.x;
    if (i < N_NODES * HF) d_acc[i] = 0.f;
    if (i < N_NODES * NHEAD) {
        d_m[i]   = __int_as_float(0xff800000);   // -inf
        d_den[i] = 0.f;
    }
}

// ---------------- edge pass A: e = leakyrelu(s[src]+d[dst]); segment max ----------------
__global__ void edge_a_kernel(const int* __restrict__ ei) {
    int i = blockIdx.x * blockDim.x + threadIdx.x;
    if (i >= EE_TOT) return;
    int s, d;
    if (i < N_EDGES) { s = ei[i]; d = ei[N_EDGES + i]; }
    else             { s = d = i - N_EDGES; }
    float4 sv = *(const float4*)&d_s[s * 4];
    float4 dv = *(const float4*)&d_dt[d * 4];
    float4 e;
    e.x = lrelu(sv.x + dv.x);
    e.y = lrelu(sv.y + dv.y);
    e.z = lrelu(sv.z + dv.z);
    e.w = lrelu(sv.w + dv.w);
    *(float4*)&d_e[i * 4] = e;
    atomicMaxF(&d_m[d * 4 + 0], e.x);
    atomicMaxF(&d_m[d * 4 + 1], e.y);
    atomicMaxF(&d_m[d * 4 + 2], e.z);
    atomicMaxF(&d_m[d * 4 + 3], e.w);
}

// ---------------- edge pass B: ex = exp(e - m[dst]); segment sum ----------------
__global__ void edge_b_kernel(const int* __restrict__ ei) {
    int i = blockIdx.x * blockDim.x + threadIdx.x;
    if (i >= EE_TOT) return;
    int d = (i < N_EDGES) ? ei[N_EDGES + i] : (i - N_EDGES);
    float4 e = *(const float4*)&d_e[i * 4];
    float4 m = *(const float4*)&d_m[d * 4];
    float4 ex;
    ex.x = __expf(e.x - m.x);
    ex.y = __expf(e.y - m.y);
    ex.z = __expf(e.z - m.z);
    ex.w = __expf(e.w - m.w);
    *(float4*)&d_e[i * 4] = ex;
    red_add_f4(&d_den[d * 4], ex.x, ex.y, ex.z, ex.w);
}

__global__ void inv_den_kernel() {
    int i = blockIdx.x * blockDim.x + threadIdx.x;
    if (i < N_NODES * NHEAD) d_den[i] = 1.0f / d_den[i];
}

// ---------------- edge pass C: acc[dst] += alpha * h[src]  (warp per edge) ----------------
__global__ void edge_c_kernel(const int* __restrict__ ei) {
    int gid  = blockIdx.x * blockDim.x + threadIdx.x;
    int e    = gid >> 5;
    if (e >= EE_TOT) return;
    int lane = gid & 31;
    int s, d;
    if (e < N_EDGES) { s = ei[e]; d = ei[N_EDGES + e]; }
    else             { s = d = e - N_EDGES; }
    float4 ex = *(const float4*)&d_e[e * 4];
    float4 rd = *(const float4*)&d_den[d * 4];    // reciprocal of den
    float al[4] = { ex.x * rd.x, ex.y * rd.y, ex.z * rd.z, ex.w * rd.w };
    const float4* hp = (const float4*)&d_h[(size_t)s * HF];
    float4* ap = (float4*)&d_acc[(size_t)d * HF];
    #pragma unroll
    for (int t = 0; t < 2; t++) {
        int c4 = lane + 32 * t;          // float4 index in 0..63
        float a = al[c4 >> 4];           // head = (c4*4)/64
        float4 hv = hp[c4];
        red_add_f4((float*)(ap + c4), a * hv.x, a * hv.y, a * hv.z, a * hv.w);
    }
}

// ---------------- finalize: x = relu(acc + b); pool into g ----------------
__global__ void finalize_kernel(const float* __restrict__ bias,
                                const int* __restrict__ batch,
                                float* __restrict__ xout, int goff)
{
    int i = blockIdx.x * blockDim.x + threadIdx.x;
    if (i >= N_NODES * HF) return;
    int n = i >> 8;
    int c = i & 255;
    float v = fmaxf(d_acc[i] + bias[c], 0.f);
    xout[i] = v;
    atomicMax((int*)&d_g[batch[n] * GCOLS + goff + c], __float_as_int(v));  // v >= 0
}

// ---------------- launch ----------------
extern "C" void kernel_launch(void* const* d_in, const int* in_sizes, int n_in,
                              void* d_out, int out_size)
{
    const float* sfeat = (const float*)d_in[0];
    const float* bfeat = (const float*)d_in[1];
    const float* smask = (const float*)d_in[2];
    const float* bmask = (const float*)d_in[3];
    const int*   ei    = (const int*)  d_in[4];
    const int*   batch = (const int*)  d_in[5];
    const float* sW    = (const float*)d_in[6];
    const float* sb    = (const float*)d_in[7];
    const float* bW    = (const float*)d_in[8];
    const float* bb    = (const float*)d_in[9];
    const float* W[3]  = {(const float*)d_in[10], (const float*)d_in[14], (const float*)d_in[18]};
    const float* asr[3]= {(const float*)d_in[11], (const float*)d_in[15], (const float*)d_in[19]};
    const float* ads[3]= {(const float*)d_in[12], (const float*)d_in[16], (const float*)d_in[20]};
    const float* bl[3] = {(const float*)d_in[13], (const float*)d_in[17], (const float*)d_in[21]};
    const float* aggW  = (const float*)d_in[22];
    const float* aggb  = (const float*)d_in[23];
    const float* muW   = (const float*)d_in[24];
    const float* mub   = (const float*)d_in[25];
    const float* varW  = (const float*)d_in[26];
    const float* varb  = (const float*)d_in[27];
    float* out = (float*)d_out;

    float *px, *ph, *pn0, *pg, *plat;
    cudaGetSymbolAddress((void**)&px,   d_x);
    cudaGetSymbolAddress((void**)&ph,   d_h);
    cudaGetSymbolAddress((void**)&pn0,  d_n0);
    cudaGetSymbolAddress((void**)&pg,   d_g);
    cudaGetSymbolAddress((void**)&plat, d_lat);

    zero_g_kernel<<<(NGR * GCOLS + 255) / 256, 256>>>();
    node_init_kernel<<<N_NODES / 16, 256>>>(sfeat, bfeat, smask, bmask, sW, sb, bW, bb, batch);

    for (int l = 0; l < 3; l++) {
        const float* xin = (l == 0) ? pn0 : px;
        int Kin = (l == 0) ? FDIM : HF;
        dim3 gg((N_NODES + 127) / 128, HF / 64);
        sgemm_tn<128, 64, 16, 8, 4, 256><<<gg, 256>>>(xin, W[l], nullptr, ph, N_NODES, HF, Kin);
        attn_scores_kernel<<<(N_NODES + 7) / 8, 256>>>(ph, asr[l], ads[l]);
        init_layer_kernel<<<(N_NODES * HF + 255) / 256, 256>>>();
        edge_a_kernel<<<(EE_TOT + 255) / 256, 256>>>(ei);
        edge_b_kernel<<<(EE_TOT + 255) / 256, 256>>>(ei);
        inv_den_kernel<<<(N_NODES * NHEAD + 255) / 256, 256>>>();
        edge_c_kernel<<<(EE_TOT * 32 + 255) / 256, 256>>>(ei);
        finalize_kernel<<<(N_NODES * HF + 255) / 256, 256>>>(bl[l], batch, px, FDIM + l * HF);
    }

    // g [64,832] -> latent [64,512] -> mu / log_var [64,512]
    dim3 gl((NGR + 15) / 16, LATD / 64);
    sgemm_tn<16, 64, 16, 2, 4, 128><<<gl, 128>>>(pg,   aggW, aggb, plat, NGR, LATD, GCOLS);
    sgemm_tn<16, 64, 16, 2, 4, 128><<<gl, 128>>>(plat, muW,  mub,  out,              NGR, LATD, LATD);
    sgemm_tn<16, 64, 16, 2, 4, 128><<<gl, 128>>>(plat, varW, varb, out + NGR * LATD, NGR, LATD, LATD);
}

// round 5
// speedup vs baseline: 1.1219x; 1.1219x over previous
#include <cuda_runtime.h>
#include <math.h>

// Problem constants
#define N_NODES 20000
#define N_EDGES 320000
#define EE_TOT  (N_EDGES + N_NODES)   // with self loops
#define FDIM    64
#define NHEAD   4
#define HF      256                   // NHEAD * FDIM
#define NGR     64
#define LATD    512
#define GCOLS   832                   // FDIM * (1 + 3*NHEAD)

// -------- scratch (static device globals; no allocation allowed) --------
static __device__ __align__(16) float d_n0 [N_NODES * FDIM];
static __device__ __align__(16) float d_x  [N_NODES * HF];
static __device__ __align__(16) float d_h  [N_NODES * HF];
static __device__ __align__(16) float d_s  [N_NODES * NHEAD];
static __device__ __align__(16) float d_dt [N_NODES * NHEAD];
static __device__ __align__(16) float d_den[N_NODES * NHEAD];
static __device__ __align__(16) float d_e  [EE_TOT * NHEAD];
static __device__ __align__(16) float d_g  [NGR * GCOLS];
static __device__ __align__(16) float d_lat[NGR * LATD];
// CSR (built per launch, reused by all 3 layers)
static __device__ int d_deg  [N_NODES + 1];
static __device__ int d_start[N_NODES + 1];
static __device__ int d_fill [N_NODES];
static __device__ int d_csrc [EE_TOT];

__device__ __forceinline__ float lrelu(float x) { return x > 0.f ? x : 0.2f * x; }

// ---------------- zero pass: g buffer + CSR counters ----------------
__global__ void zero_kernel() {
    int i = blockIdx.x * blockDim.x + threadIdx.x;
    if (i < NGR * GCOLS) d_g[i] = 0.f;
    if (i <= N_NODES)    d_deg[i] = 0;
    if (i < N_NODES)     d_fill[i] = 0;
}

// ---------------- CSR build ----------------
__global__ void count_deg_kernel(const int* __restrict__ ei) {
    int i = blockIdx.x * blockDim.x + threadIdx.x;
    if (i >= EE_TOT) return;
    int d = (i < N_EDGES) ? ei[N_EDGES + i] : (i - N_EDGES);
    atomicAdd(&d_deg[d], 1);
}

__global__ void scan_deg_kernel() {
    __shared__ int partial[1024];
    int t = threadIdx.x;
    const int CH = (N_NODES + 1023) / 1024;   // 20
    int b0 = t * CH;
    int bend = min(b0 + CH, N_NODES);
    int sum = 0;
    for (int i = b0; i < bend; i++) sum += d_deg[i];
    partial[t] = sum;
    __syncthreads();
    for (int off = 1; off < 1024; off <<= 1) {
        int v = (t >= off) ? partial[t - off] : 0;
        __syncthreads();
        partial[t] += v;
        __syncthreads();
    }
    int run = (t == 0) ? 0 : partial[t - 1];
    for (int i = b0; i < bend; i++) {
        d_start[i] = run;
        run += d_deg[i];
    }
    if (t == 1023) d_start[N_NODES] = run;
}

__global__ void scatter_csr_kernel(const int* __restrict__ ei) {
    int i = blockIdx.x * blockDim.x + threadIdx.x;
    if (i >= EE_TOT) return;
    int s, d;
    if (i < N_EDGES) { s = ei[i]; d = ei[N_EDGES + i]; }
    else             { s = d = i - N_EDGES; }
    int slot = atomicAdd(&d_fill[d], 1);
    d_csrc[d_start[d] + slot] = s;
}

// ---------------- node feature encoders + mask mix ----------------
__global__ void node_init_kernel(const float* __restrict__ sfeat,
                                 const float* __restrict__ bfeat,
                                 const float* __restrict__ smask,
                                 const float* __restrict__ bmask,
                                 const float* __restrict__ sW,
                                 const float* __restrict__ sb,
                                 const float* __restrict__ bW,
                                 const float* __restrict__ bb)
{
    __shared__ float sWs[128 * 65];   // [k][f], padded stride 65
    __shared__ float xs[4 * 128];
    int tid = threadIdx.x;
    for (int li = tid; li < 64 * 128; li += 256) {
        int f = li >> 7;
        int k = li & 127;
        sWs[k * 65 + f] = sW[li];     // sW row-major [64,128]
    }
    __syncthreads();

    int nb0 = blockIdx.x * 16;
    for (int grp = 0; grp < 4; grp++) {
        int nb = nb0 + grp * 4;
        xs[tid]       = sfeat[nb * 128 + tid];
        xs[tid + 256] = sfeat[nb * 128 + tid + 256];
        __syncthreads();
        int ni = tid >> 6;
        int f  = tid & 63;
        int n  = nb + ni;
        float acc = sb[f];
        #pragma unroll 8
        for (int k = 0; k < 128; k++)
            acc = fmaf(xs[ni * 128 + k], sWs[k * 65 + f], acc);
        float sv = fmaxf(acc, 0.f);
        float bacc = bb[f];
        #pragma unroll
        for (int k = 0; k < 5; k++)
            bacc = fmaf(bfeat[n * 5 + k], bW[f * 5 + k], bacc);
        float bv = fmaxf(bacc, 0.f);
        d_n0[n * FDIM + f] = sv * smask[n] + bv * bmask[n];
        __syncthreads();
    }
}

// ---------------- segment-max pooling, block-local reduction ----------------
// blockDim.x = cols; each block handles 64 consecutive (batch-sorted) nodes.
__global__ void pool_max_kernel(const float* __restrict__ x,
                                const int* __restrict__ batch,
                                int cols, int goff)
{
    int t = threadIdx.x;
    int n0 = blockIdx.x * 64;
    int nend = min(n0 + 64, N_NODES);
    int curg = batch[n0];
    float mx = 0.f;                       // values are >= 0 (post-relu)
    for (int n = n0; n < nend; n++) {
        int g = batch[n];
        if (g != curg) {
            atomicMax((int*)&d_g[curg * GCOLS + goff + t], __float_as_int(mx));
            curg = g;
            mx = 0.f;
        }
        mx = fmaxf(mx, x[(size_t)n * cols + t]);
    }
    atomicMax((int*)&d_g[curg * GCOLS + goff + t], __float_as_int(mx));
}

// ---------------- generic tiled SGEMM: C[M,N] = A[M,K] @ B[N,K]^T (+bias) ----------------
template<int BM, int BN, int BK, int TM, int TN, int NT>
__global__ void sgemm_tn(const float* __restrict__ A, const float* __restrict__ B,
                         const float* __restrict__ bias, float* __restrict__ C,
                         int M, int N, int K)
{
    __shared__ float As[BK][BM];
    __shared__ float Bs[BK][BN];
    int tid = threadIdx.x;
    int tx = tid % (BN / TN);
    int ty = tid / (BN / TN);
    int m0 = blockIdx.x * BM;
    int n0 = blockIdx.y * BN;

    float acc[TM][TN];
    #pragma unroll
    for (int i = 0; i < TM; i++)
        #pragma unroll
        for (int j = 0; j < TN; j++) acc[i][j] = 0.f;

    for (int k0 = 0; k0 < K; k0 += BK) {
        #pragma unroll
        for (int li = tid; li < BM * BK / 4; li += NT) {
            int r  = li / (BK / 4);
            int c4 = li % (BK / 4);
            float4 v = make_float4(0.f, 0.f, 0.f, 0.f);
            if (m0 + r < M)
                v = *(const float4*)&A[(size_t)(m0 + r) * K + k0 + c4 * 4];
            As[c4 * 4 + 0][r] = v.x;
            As[c4 * 4 + 1][r] = v.y;
            As[c4 * 4 + 2][r] = v.z;
            As[c4 * 4 + 3][r] = v.w;
        }
        #pragma unroll
        for (int li = tid; li < BN * BK / 4; li += NT) {
            int r  = li / (BK / 4);
            int c4 = li % (BK / 4);
            float4 v = *(const float4*)&B[(size_t)(n0 + r) * K + k0 + c4 * 4];
            Bs[c4 * 4 + 0][r] = v.x;
            Bs[c4 * 4 + 1][r] = v.y;
            Bs[c4 * 4 + 2][r] = v.z;
            Bs[c4 * 4 + 3][r] = v.w;
        }
        __syncthreads();
        #pragma unroll
        for (int k = 0; k < BK; k++) {
            float a[TM], b[TN];
            #pragma unroll
            for (int i = 0; i < TM; i++) a[i] = As[k][ty * TM + i];
            #pragma unroll
            for (int j = 0; j < TN; j++) b[j] = Bs[k][tx * TN + j];
            #pragma unroll
            for (int i = 0; i < TM; i++)
                #pragma unroll
                for (int j = 0; j < TN; j++)
                    acc[i][j] = fmaf(a[i], b[j], acc[i][j]);
        }
        __syncthreads();
    }

    #pragma unroll
    for (int i = 0; i < TM; i++) {
        int row = m0 + ty * TM + i;
        if (row >= M) continue;
        #pragma unroll
        for (int j = 0; j < TN; j++) {
            int col = n0 + tx * TN + j;
            float v = acc[i][j];
            if (bias) v += bias[col];
            C[(size_t)row * N + col] = v;
        }
    }
}

// ---------------- per-node attention scores s,d (warp per node, float4) ----------------
__global__ void attn_scores_kernel(const float* __restrict__ h,
                                   const float* __restrict__ asrc,
                                   const float* __restrict__ adst)
{
    int w = (blockIdx.x * blockDim.x + threadIdx.x) >> 5;
    if (w >= N_NODES) return;
    int lane = threadIdx.x & 31;
    const float4* hp  = (const float4*)(h + (size_t)w * HF);   // 64 float4
    const float4* as4 = (const float4*)asrc;
    const float4* ad4 = (const float4*)adst;

    float4 h0 = hp[lane],       h1 = hp[lane + 32];
    float4 a0 = as4[lane],      a1 = as4[lane + 32];
    float4 b0 = ad4[lane],      b1 = ad4[lane + 32];
    float ps0 = h0.x * a0.x + h0.y * a0.y + h0.z * a0.z + h0.w * a0.w;
    float pd0 = h0.x * b0.x + h0.y * b0.y + h0.z * b0.z + h0.w * b0.w;
    float ps1 = h1.x * a1.x + h1.y * a1.y + h1.z * a1.z + h1.w * a1.w;
    float pd1 = h1.x * b1.x + h1.y * b1.y + h1.z * b1.z + h1.w * b1.w;
    // reduce within 16-lane groups (lane 0-15 = head0/2, 16-31 = head1/3)
    #pragma unroll
    for (int off = 8; off > 0; off >>= 1) {
        ps0 += __shfl_xor_sync(0xFFFFFFFFu, ps0, off);
        pd0 += __shfl_xor_sync(0xFFFFFFFFu, pd0, off);
        ps1 += __shfl_xor_sync(0xFFFFFFFFu, ps1, off);
        pd1 += __shfl_xor_sync(0xFFFFFFFFu, pd1, off);
    }
    if ((lane & 15) == 0) {
        int hh = lane >> 4;                   // 0 or 1
        d_s [w * 4 + hh]     = ps0;
        d_s [w * 4 + 2 + hh] = ps1;
        d_dt[w * 4 + hh]     = pd0;
        d_dt[w * 4 + 2 + hh] = pd1;
    }
}

// ---------------- fused edge softmax (warp per dst node, CSR) ----------------
// writes d_e[j*4] = exp(e - max) per edge, d_den[node*4] = 1/sum per head
__global__ void csr_softmax_kernel() {
    int w = (blockIdx.x * blockDim.x + threadIdx.x) >> 5;
    if (w >= N_NODES) return;
    int lane = threadIdx.x & 31;
    int js = d_start[w], je = d_start[w + 1];
    float4 dv = *(const float4*)&d_dt[w * 4];

    float m0 = -INFINITY, m1 = -INFINITY, m2 = -INFINITY, m3 = -INFINITY;
    for (int j = js + lane; j < je; j += 32) {
        int src = d_csrc[j];
        float4 sv = __ldg((const float4*)&d_s[src * 4]);
        float4 e;
        e.x = lrelu(sv.x + dv.x);
        e.y = lrelu(sv.y + dv.y);
        e.z = lrelu(sv.z + dv.z);
        e.w = lrelu(sv.w + dv.w);
        *(float4*)&d_e[j * 4] = e;
        m0 = fmaxf(m0, e.x); m1 = fmaxf(m1, e.y);
        m2 = fmaxf(m2, e.z); m3 = fmaxf(m3, e.w);
    }
    #pragma unroll
    for (int off = 16; off > 0; off >>= 1) {
        m0 = fmaxf(m0, __shfl_xor_sync(0xFFFFFFFFu, m0, off));
        m1 = fmaxf(m1, __shfl_xor_sync(0xFFFFFFFFu, m1, off));
        m2 = fmaxf(m2, __shfl_xor_sync(0xFFFFFFFFu, m2, off));
        m3 = fmaxf(m3, __shfl_xor_sync(0xFFFFFFFFu, m3, off));
    }
    float s0 = 0.f, s1 = 0.f, s2 = 0.f, s3 = 0.f;
    for (int j = js + lane; j < je; j += 32) {
        float4 e = *(const float4*)&d_e[j * 4];
        float4 ex;
        ex.x = __expf(e.x - m0); ex.y = __expf(e.y - m1);
        ex.z = __expf(e.z - m2); ex.w = __expf(e.w - m3);
        *(float4*)&d_e[j * 4] = ex;
        s0 += ex.x; s1 += ex.y; s2 += ex.z; s3 += ex.w;
    }
    #pragma unroll
    for (int off = 16; off > 0; off >>= 1) {
        s0 += __shfl_xor_sync(0xFFFFFFFFu, s0, off);
        s1 += __shfl_xor_sync(0xFFFFFFFFu, s1, off);
        s2 += __shfl_xor_sync(0xFFFFFFFFu, s2, off);
        s3 += __shfl_xor_sync(0xFFFFFFFFu, s3, off);
    }
    if (lane == 0) {
        float4 r;
        r.x = 1.0f / s0; r.y = 1.0f / s1; r.z = 1.0f / s2; r.w = 1.0f / s3;
        *(float4*)&d_den[w * 4] = r;
    }
}

// ---------------- CSR aggregation (warp per dst node, register acc, no atomics) ----------------
// x[w] = relu( (1/den) * sum_j ex_j * h[src_j] + bias )
__global__ void csr_agg_kernel(const float* __restrict__ h,
                               const float* __restrict__ bias,
                               float* __restrict__ xout)
{
    int w = (blockIdx.x * blockDim.x + threadIdx.x) >> 5;
    if (w >= N_NODES) return;
    int lane = threadIdx.x & 31;
    int js = d_start[w], je = d_start[w + 1];

    float4 acc0 = make_float4(0.f, 0.f, 0.f, 0.f);
    float4 acc1 = make_float4(0.f, 0.f, 0.f, 0.f);
    bool lo = lane < 16;  // float4 idx lane  -> head 0/1 ; lane+32 -> head 2/3

    for (int j = js; j < je; j++) {
        int src = d_csrc[j];                               // broadcast
        float4 a4 = __ldg((const float4*)&d_e[j * 4]);     // broadcast
        float a_lo = lo ? a4.x : a4.y;
        float a_hi = lo ? a4.z : a4.w;
        const float4* hp4 = (const float4*)(h + (size_t)src * HF);
        float4 h0 = __ldg(&hp4[lane]);
        float4 h1 = __ldg(&hp4[lane + 32]);
        acc0.x = fmaf(a_lo, h0.x, acc0.x);
        acc0.y = fmaf(a_lo, h0.y, acc0.y);
        acc0.z = fmaf(a_lo, h0.z, acc0.z);
        acc0.w = fmaf(a_lo, h0.w, acc0.w);
        acc1.x = fmaf(a_hi, h1.x, acc1.x);
        acc1.y = fmaf(a_hi, h1.y, acc1.y);
        acc1.z = fmaf(a_hi, h1.z, acc1.z);
        acc1.w = fmaf(a_hi, h1.w, acc1.w);
    }

    float4 rd = *(const float4*)&d_den[w * 4];
    float r_lo = lo ? rd.x : rd.y;
    float r_hi = lo ? rd.z : rd.w;
    const float4* bi4 = (const float4*)bias;
    float4 bb0 = __ldg(&bi4[lane]);
    float4 bb1 = __ldg(&bi4[lane + 32]);
    float4 v0, v1;
    v0.x = fmaxf(fmaf(acc0.x, r_lo, bb0.x), 0.f);
    v0.y = fmaxf(fmaf(acc0.y, r_lo, bb0.y), 0.f);
    v0.z = fmaxf(fmaf(acc0.z, r_lo, bb0.z), 0.f);
    v0.w = fmaxf(fmaf(acc0.w, r_lo, bb0.w), 0.f);
    v1.x = fmaxf(fmaf(acc1.x, r_hi, bb1.x), 0.f);
    v1.y = fmaxf(fmaf(acc1.y, r_hi, bb1.y), 0.f);
    v1.z = fmaxf(fmaf(acc1.z, r_hi, bb1.z), 0.f);
    v1.w = fmaxf(fmaf(acc1.w, r_hi, bb1.w), 0.f);
    float4* xo = (float4*)(xout + (size_t)w * HF);
    xo[lane]      = v0;
    xo[lane + 32] = v1;
}

// ---------------- launch ----------------
extern "C" void kernel_launch(void* const* d_in, const int* in_sizes, int n_in,
                              void* d_out, int out_size)
{
    const float* sfeat = (const float*)d_in[0];
    const float* bfeat = (const float*)d_in[1];
    const float* smask = (const float*)d_in[2];
    const float* bmask = (const float*)d_in[3];
    const int*   ei    = (const int*)  d_in[4];
    const int*   batch = (const int*)  d_in[5];
    const float* sW    = (const float*)d_in[6];
    const float* sb    = (const float*)d_in[7];
    const float* bW    = (const float*)d_in[8];
    const float* bb    = (const float*)d_in[9];
    const float* W[3]  = {(const float*)d_in[10], (const float*)d_in[14], (const float*)d_in[18]};
    const float* asr[3]= {(const float*)d_in[11], (const float*)d_in[15], (const float*)d_in[19]};
    const float* ads[3]= {(const float*)d_in[12], (const float*)d_in[16], (const float*)d_in[20]};
    const float* bl[3] = {(const float*)d_in[13], (const float*)d_in[17], (const float*)d_in[21]};
    const float* aggW  = (const float*)d_in[22];
    const float* aggb  = (const float*)d_in[23];
    const float* muW   = (const float*)d_in[24];
    const float* mub   = (const float*)d_in[25];
    const float* varW  = (const float*)d_in[26];
    const float* varb  = (const float*)d_in[27];
    float* out = (float*)d_out;

    float *px, *ph, *pn0, *pg, *plat;
    cudaGetSymbolAddress((void**)&px,   d_x);
    cudaGetSymbolAddress((void**)&ph,   d_h);
    cudaGetSymbolAddress((void**)&pn0,  d_n0);
    cudaGetSymbolAddress((void**)&pg,   d_g);
    cudaGetSymbolAddress((void**)&plat, d_lat);

    // zero + CSR build (reused across layers)
    zero_kernel<<<(NGR * GCOLS + 255) / 256, 256>>>();
    count_deg_kernel<<<(EE_TOT + 255) / 256, 256>>>(ei);
    scan_deg_kernel<<<1, 1024>>>();
    scatter_csr_kernel<<<(EE_TOT + 255) / 256, 256>>>(ei);

    node_init_kernel<<<N_NODES / 16, 256>>>(sfeat, bfeat, smask, bmask, sW, sb, bW, bb);
    pool_max_kernel<<<(N_NODES + 63) / 64, FDIM>>>(pn0, batch, FDIM, 0);

    for (int l = 0; l < 3; l++) {
        const float* xin = (l == 0) ? pn0 : px;
        int Kin = (l == 0) ? FDIM : HF;
        dim3 gg((N_NODES + 127) / 128, HF / 128);
        sgemm_tn<128, 128, 16, 8, 8, 256><<<gg, 256>>>(xin, W[l], nullptr, ph, N_NODES, HF, Kin);
        attn_scores_kernel<<<(N_NODES + 7) / 8, 256>>>(ph, asr[l], ads[l]);
        csr_softmax_kernel<<<(N_NODES + 7) / 8, 256>>>();
        csr_agg_kernel<<<(N_NODES + 7) / 8, 256>>>(ph, bl[l], px);
        pool_max_kernel<<<(N_NODES + 63) / 64, HF>>>(px, batch, HF, FDIM + l * HF);
    }

    // g [64,832] -> latent [64,512] -> mu / log_var [64,512]
    dim3 gl((NGR + 15) / 16, LATD / 64);
    sgemm_tn<16, 64, 16, 2, 4, 128><<<gl, 128>>>(pg,   aggW, aggb, plat, NGR, LATD, GCOLS);
    sgemm_tn<16, 64, 16, 2, 4, 128><<<gl, 128>>>(plat, muW,  mub,  out,              NGR, LATD, LATD);
    sgemm_tn<16, 64, 16, 2, 4, 128><<<gl, 128>>>(plat, varW, varb, out + NGR * LATD, NGR, LATD, LATD);
}

// round 6
// speedup vs baseline: 1.4216x; 1.2672x over previous
#include <cuda_runtime.h>
#include <math.h>

// Problem constants
#define N_NODES 20000
#define N_EDGES 320000
#define EE_TOT  (N_EDGES + N_NODES)   // with self loops
#define FDIM    64
#define NHEAD   4
#define HF      256                   // NHEAD * FDIM
#define NGR     64
#define LATD    512
#define GCOLS   832                   // FDIM * (1 + 3*NHEAD)

// -------- scratch (static device globals; no allocation allowed) --------
static __device__ __align__(16) float d_n0 [N_NODES * FDIM];
static __device__ __align__(16) float d_x  [N_NODES * HF];
static __device__ __align__(16) float d_h  [N_NODES * HF];
static __device__ __align__(16) float d_s  [N_NODES * NHEAD];
static __device__ __align__(16) float d_dt [N_NODES * NHEAD];
static __device__ __align__(16) float d_g  [NGR * GCOLS];
static __device__ __align__(16) float d_lat[NGR * LATD];
// CSR (built per launch, reused by all 3 layers)
static __device__ int d_deg  [N_NODES + 1];
static __device__ int d_start[N_NODES + 1];
static __device__ int d_fill [N_NODES];
static __device__ int d_csrc [EE_TOT];

__device__ __forceinline__ float lrelu(float x) { return x > 0.f ? x : 0.2f * x; }

// ---------------- zero pass: g buffer + CSR counters ----------------
__global__ void zero_kernel() {
    int i = blockIdx.x * blockDim.x + threadIdx.x;
    if (i < NGR * GCOLS) d_g[i] = 0.f;
    if (i <= N_NODES)    d_deg[i] = 0;
    if (i < N_NODES)     d_fill[i] = 0;
}

// ---------------- CSR build ----------------
__global__ void count_deg_kernel(const int* __restrict__ ei) {
    int i = blockIdx.x * blockDim.x + threadIdx.x;
    if (i >= EE_TOT) return;
    int d = (i < N_EDGES) ? ei[N_EDGES + i] : (i - N_EDGES);
    atomicAdd(&d_deg[d], 1);
}

__global__ void scan_deg_kernel() {
    __shared__ int partial[1024];
    int t = threadIdx.x;
    const int CH = (N_NODES + 1023) / 1024;   // 20
    int b0 = t * CH;
    int bend = min(b0 + CH, N_NODES);
    int sum = 0;
    for (int i = b0; i < bend; i++) sum += d_deg[i];
    partial[t] = sum;
    __syncthreads();
    for (int off = 1; off < 1024; off <<= 1) {
        int v = (t >= off) ? partial[t - off] : 0;
        __syncthreads();
        partial[t] += v;
        __syncthreads();
    }
    int run = (t == 0) ? 0 : partial[t - 1];
    for (int i = b0; i < bend; i++) {
        d_start[i] = run;
        run += d_deg[i];
    }
    if (t == 1023) d_start[N_NODES] = run;
}

__global__ void scatter_csr_kernel(const int* __restrict__ ei) {
    int i = blockIdx.x * blockDim.x + threadIdx.x;
    if (i >= EE_TOT) return;
    int s, d;
    if (i < N_EDGES) { s = ei[i]; d = ei[N_EDGES + i]; }
    else             { s = d = i - N_EDGES; }
    int slot = atomicAdd(&d_fill[d], 1);
    d_csrc[d_start[d] + slot] = s;
}

// ---------------- node feature encoders + mask mix ----------------
__global__ void node_init_kernel(const float* __restrict__ sfeat,
                                 const float* __restrict__ bfeat,
                                 const float* __restrict__ smask,
                                 const float* __restrict__ bmask,
                                 const float* __restrict__ sW,
                                 const float* __restrict__ sb,
                                 const float* __restrict__ bW,
                                 const float* __restrict__ bb)
{
    __shared__ float sWs[128 * 65];   // [k][f], padded stride 65
    __shared__ float xs[4 * 128];
    int tid = threadIdx.x;
    for (int li = tid; li < 64 * 128; li += 256) {
        int f = li >> 7;
        int k = li & 127;
        sWs[k * 65 + f] = sW[li];     // sW row-major [64,128]
    }
    __syncthreads();

    int nb0 = blockIdx.x * 16;
    for (int grp = 0; grp < 4; grp++) {
        int nb = nb0 + grp * 4;
        xs[tid]       = sfeat[nb * 128 + tid];
        xs[tid + 256] = sfeat[nb * 128 + tid + 256];
        __syncthreads();
        int ni = tid >> 6;
        int f  = tid & 63;
        int n  = nb + ni;
        float acc = sb[f];
        #pragma unroll 8
        for (int k = 0; k < 128; k++)
            acc = fmaf(xs[ni * 128 + k], sWs[k * 65 + f], acc);
        float sv = fmaxf(acc, 0.f);
        float bacc = bb[f];
        #pragma unroll
        for (int k = 0; k < 5; k++)
            bacc = fmaf(bfeat[n * 5 + k], bW[f * 5 + k], bacc);
        float bv = fmaxf(bacc, 0.f);
        d_n0[n * FDIM + f] = sv * smask[n] + bv * bmask[n];
        __syncthreads();
    }
}

// ---------------- segment-max pooling, block-local reduction ----------------
__global__ void pool_max_kernel(const float* __restrict__ x,
                                const int* __restrict__ batch,
                                int cols, int goff)
{
    int t = threadIdx.x;
    int n0 = blockIdx.x * 64;
    int nend = min(n0 + 64, N_NODES);
    int curg = batch[n0];
    float mx = 0.f;                       // values are >= 0 (post-relu)
    for (int n = n0; n < nend; n++) {
        int g = batch[n];
        if (g != curg) {
            atomicMax((int*)&d_g[curg * GCOLS + goff + t], __float_as_int(mx));
            curg = g;
            mx = 0.f;
        }
        mx = fmaxf(mx, x[(size_t)n * cols + t]);
    }
    atomicMax((int*)&d_g[curg * GCOLS + goff + t], __float_as_int(mx));
}

// ---------------- h-GEMM (128x128x16, 8x8), reg-prefetch, fused attn epilogue -----
// C[M,HF] = A[M,K] @ B[HF,K]^T ; also writes d_s/d_dt (attention scores).
__global__ __launch_bounds__(256, 2)
void sgemm_attn(const float* __restrict__ A, const float* __restrict__ B,
                float* __restrict__ C, int M, int K,
                const float* __restrict__ asrc, const float* __restrict__ adst)
{
    __shared__ float As[16][132];
    __shared__ float Bs[16][132];
    int tid  = threadIdx.x;
    int tx   = tid & 15;
    int ty   = tid >> 4;
    int lane = tid & 31;
    int m0 = blockIdx.x * 128;
    int n0 = blockIdx.y * 128;

    float4 ra[2], rb[2];
    #pragma unroll
    for (int t = 0; t < 2; t++) {
        int li = tid + t * 256;
        int r = li >> 2, c4 = li & 3;
        ra[t] = (m0 + r < M) ? *(const float4*)&A[(size_t)(m0 + r) * K + c4 * 4]
                             : make_float4(0.f, 0.f, 0.f, 0.f);
        rb[t] = *(const float4*)&B[(size_t)(n0 + r) * K + c4 * 4];
    }

    float acc[8][8];
    #pragma unroll
    for (int i = 0; i < 8; i++)
        #pragma unroll
        for (int j = 0; j < 8; j++) acc[i][j] = 0.f;

    for (int k0 = 0;;) {
        #pragma unroll
        for (int t = 0; t < 2; t++) {
            int li = tid + t * 256;
            int r = li >> 2, c4 = li & 3;
            As[c4 * 4 + 0][r] = ra[t].x; As[c4 * 4 + 1][r] = ra[t].y;
            As[c4 * 4 + 2][r] = ra[t].z; As[c4 * 4 + 3][r] = ra[t].w;
            Bs[c4 * 4 + 0][r] = rb[t].x; Bs[c4 * 4 + 1][r] = rb[t].y;
            Bs[c4 * 4 + 2][r] = rb[t].z; Bs[c4 * 4 + 3][r] = rb[t].w;
        }
        __syncthreads();
        int k0n = k0 + 16;
        if (k0n < K) {
            // prefetch next tile (issues before compute -> latency hidden)
            #pragma unroll
            for (int t = 0; t < 2; t++) {
                int li = tid + t * 256;
                int r = li >> 2, c4 = li & 3;
                ra[t] = (m0 + r < M) ? *(const float4*)&A[(size_t)(m0 + r) * K + k0n + c4 * 4]
                                     : make_float4(0.f, 0.f, 0.f, 0.f);
                rb[t] = *(const float4*)&B[(size_t)(n0 + r) * K + k0n + c4 * 4];
            }
        }
        #pragma unroll
        for (int k = 0; k < 16; k++) {
            float4 a0 = *(const float4*)&As[k][ty * 8];
            float4 a1 = *(const float4*)&As[k][ty * 8 + 4];
            float4 b0 = *(const float4*)&Bs[k][tx * 4];
            float4 b1 = *(const float4*)&Bs[k][64 + tx * 4];
            float a[8] = {a0.x, a0.y, a0.z, a0.w, a1.x, a1.y, a1.z, a1.w};
            float b[8] = {b0.x, b0.y, b0.z, b0.w, b1.x, b1.y, b1.z, b1.w};
            #pragma unroll
            for (int i = 0; i < 8; i++)
                #pragma unroll
                for (int j = 0; j < 8; j++)
                    acc[i][j] = fmaf(a[i], b[j], acc[i][j]);
        }
        if (k0n >= K) break;
        __syncthreads();
        k0 = k0n;
    }

    // ---- epilogue: store C ----
    #pragma unroll
    for (int i = 0; i < 8; i++) {
        int row = m0 + ty * 8 + i;
        if (row < M) {
            float4 c0 = make_float4(acc[i][0], acc[i][1], acc[i][2], acc[i][3]);
            float4 c1 = make_float4(acc[i][4], acc[i][5], acc[i][6], acc[i][7]);
            *(float4*)&C[(size_t)row * HF + n0 + tx * 4]      = c0;
            *(float4*)&C[(size_t)row * HF + n0 + 64 + tx * 4] = c1;
        }
    }
    // ---- epilogue: attention scores s,d (block uniquely owns heads headA/headB)
    float4 asA = *(const float4*)&asrc[n0 + tx * 4];
    float4 asB = *(const float4*)&asrc[n0 + 64 + tx * 4];
    float4 adA = *(const float4*)&adst[n0 + tx * 4];
    float4 adB = *(const float4*)&adst[n0 + 64 + tx * 4];
    int headA = n0 >> 6;
    int headB = headA + 1;
    #pragma unroll
    for (int i = 0; i < 8; i++) {
        float psA = acc[i][0] * asA.x + acc[i][1] * asA.y + acc[i][2] * asA.z + acc[i][3] * asA.w;
        float pdA = acc[i][0] * adA.x + acc[i][1] * adA.y + acc[i][2] * adA.z + acc[i][3] * adA.w;
        float psB = acc[i][4] * asB.x + acc[i][5] * asB.y + acc[i][6] * asB.z + acc[i][7] * asB.w;
        float pdB = acc[i][4] * adB.x + acc[i][5] * adB.y + acc[i][6] * adB.z + acc[i][7] * adB.w;
        #pragma unroll
        for (int off = 8; off > 0; off >>= 1) {
            psA += __shfl_down_sync(0xFFFFFFFFu, psA, off, 16);
            pdA += __shfl_down_sync(0xFFFFFFFFu, pdA, off, 16);
            psB += __shfl_down_sync(0xFFFFFFFFu, psB, off, 16);
            pdB += __shfl_down_sync(0xFFFFFFFFu, pdB, off, 16);
        }
        int row = m0 + ty * 8 + i;
        if ((lane & 15) == 0 && row < M) {
            d_s [row * 4 + headA] = psA;
            d_s [row * 4 + headB] = psB;
            d_dt[row * 4 + headA] = pdA;
            d_dt[row * 4 + headB] = pdB;
        }
    }
}

// ---------------- fused softmax + aggregation (warp per dst node) ----------------
// x[w] = relu( rinv * sum_j exp(e_j - max) * h[src_j] + bias )
__global__ void csr_attn_agg_kernel(const float* __restrict__ h,
                                    const float* __restrict__ bias,
                                    float* __restrict__ xout)
{
    __shared__ float4 sEx[8][64];
    int warp = threadIdx.x >> 5;
    int lane = threadIdx.x & 31;
    int w = blockIdx.x * 8 + warp;
    if (w >= N_NODES) return;
    int js = d_start[w], je = d_start[w + 1];
    int deg = je - js;
    float4 dv = *(const float4*)&d_dt[w * 4];

    // ---- pass 1: logits in registers (2 slots cover deg<=64), running max ----
    float4 e0 = make_float4(0.f, 0.f, 0.f, 0.f);
    float4 e1 = make_float4(0.f, 0.f, 0.f, 0.f);
    float m0 = -INFINITY, m1 = -INFINITY, m2 = -INFINITY, m3 = -INFINITY;
    int j0 = js + lane;
    bool v0 = j0 < je;
    bool v1 = j0 + 32 < je;
    if (v0) {
        int s = d_csrc[j0];
        float4 sv = __ldg((const float4*)&d_s[s * 4]);
        e0.x = lrelu(sv.x + dv.x); e0.y = lrelu(sv.y + dv.y);
        e0.z = lrelu(sv.z + dv.z); e0.w = lrelu(sv.w + dv.w);
        m0 = e0.x; m1 = e0.y; m2 = e0.z; m3 = e0.w;
    }
    if (v1) {
        int s = d_csrc[j0 + 32];
        float4 sv = __ldg((const float4*)&d_s[s * 4]);
        e1.x = lrelu(sv.x + dv.x); e1.y = lrelu(sv.y + dv.y);
        e1.z = lrelu(sv.z + dv.z); e1.w = lrelu(sv.w + dv.w);
        m0 = fmaxf(m0, e1.x); m1 = fmaxf(m1, e1.y);
        m2 = fmaxf(m2, e1.z); m3 = fmaxf(m3, e1.w);
    }
    for (int j = j0 + 64; j < je; j += 32) {     // rare (deg > 64)
        int s = d_csrc[j];
        float4 sv = __ldg((const float4*)&d_s[s * 4]);
        m0 = fmaxf(m0, lrelu(sv.x + dv.x)); m1 = fmaxf(m1, lrelu(sv.y + dv.y));
        m2 = fmaxf(m2, lrelu(sv.z + dv.z)); m3 = fmaxf(m3, lrelu(sv.w + dv.w));
    }
    #pragma unroll
    for (int off = 16; off > 0; off >>= 1) {
        m0 = fmaxf(m0, __shfl_xor_sync(0xFFFFFFFFu, m0, off));
        m1 = fmaxf(m1, __shfl_xor_sync(0xFFFFFFFFu, m1, off));
        m2 = fmaxf(m2, __shfl_xor_sync(0xFFFFFFFFu, m2, off));
        m3 = fmaxf(m3, __shfl_xor_sync(0xFFFFFFFFu, m3, off));
    }

    // ---- pass 2: exp + sum ----
    float s0 = 0.f, s1 = 0.f, s2 = 0.f, s3 = 0.f;
    if (v0) {
        e0.x = __expf(e0.x - m0); e0.y = __expf(e0.y - m1);
        e0.z = __expf(e0.z - m2); e0.w = __expf(e0.w - m3);
        s0 += e0.x; s1 += e0.y; s2 += e0.z; s3 += e0.w;
    }
    if (v1) {
        e1.x = __expf(e1.x - m0); e1.y = __expf(e1.y - m1);
        e1.z = __expf(e1.z - m2); e1.w = __expf(e1.w - m3);
        s0 += e1.x; s1 += e1.y; s2 += e1.z; s3 += e1.w;
    }
    for (int j = j0 + 64; j < je; j += 32) {     // rare
        int s = d_csrc[j];
        float4 sv = __ldg((const float4*)&d_s[s * 4]);
        s0 += __expf(lrelu(sv.x + dv.x) - m0);
        s1 += __expf(lrelu(sv.y + dv.y) - m1);
        s2 += __expf(lrelu(sv.z + dv.z) - m2);
        s3 += __expf(lrelu(sv.w + dv.w) - m3);
    }
    #pragma unroll
    for (int off = 16; off > 0; off >>= 1) {
        s0 += __shfl_xor_sync(0xFFFFFFFFu, s0, off);
        s1 += __shfl_xor_sync(0xFFFFFFFFu, s1, off);
        s2 += __shfl_xor_sync(0xFFFFFFFFu, s2, off);
        s3 += __shfl_xor_sync(0xFFFFFFFFu, s3, off);
    }
    float4 rinv = make_float4(1.f / s0, 1.f / s1, 1.f / s2, 1.f / s3);

    // publish exp-values to smem for warp-uniform pass 3
    sEx[warp][lane]      = e0;
    sEx[warp][lane + 32] = e1;
    __syncwarp();

    // ---- pass 3: weighted gather ----
    float4 acc0 = make_float4(0.f, 0.f, 0.f, 0.f);
    float4 acc1 = make_float4(0.f, 0.f, 0.f, 0.f);
    bool lo = lane < 16;   // float4 idx lane -> head0/1 ; lane+32 -> head2/3
    for (int jj = 0; jj < deg; jj++) {
        float4 a4;
        if (jj < 64) {
            a4 = sEx[warp][jj];                    // broadcast LDS
        } else {                                   // rare fallback: recompute
            int s = d_csrc[js + jj];
            float4 sv = __ldg((const float4*)&d_s[s * 4]);
            a4.x = __expf(lrelu(sv.x + dv.x) - m0);
            a4.y = __expf(lrelu(sv.y + dv.y) - m1);
            a4.z = __expf(lrelu(sv.z + dv.z) - m2);
            a4.w = __expf(lrelu(sv.w + dv.w) - m3);
        }
        int src = d_csrc[js + jj];                 // broadcast LDG
        float a_lo = lo ? a4.x : a4.y;
        float a_hi = lo ? a4.z : a4.w;
        const float4* hp4 = (const float4*)(h + (size_t)src * HF);
        float4 h0 = __ldg(&hp4[lane]);
        float4 h1 = __ldg(&hp4[lane + 32]);
        acc0.x = fmaf(a_lo, h0.x, acc0.x);
        acc0.y = fmaf(a_lo, h0.y, acc0.y);
        acc0.z = fmaf(a_lo, h0.z, acc0.z);
        acc0.w = fmaf(a_lo, h0.w, acc0.w);
        acc1.x = fmaf(a_hi, h1.x, acc1.x);
        acc1.y = fmaf(a_hi, h1.y, acc1.y);
        acc1.z = fmaf(a_hi, h1.z, acc1.z);
        acc1.w = fmaf(a_hi, h1.w, acc1.w);
    }

    float r_lo = lo ? rinv.x : rinv.y;
    float r_hi = lo ? rinv.z : rinv.w;
    const float4* bi4 = (const float4*)bias;
    float4 bb0 = __ldg(&bi4[lane]);
    float4 bb1 = __ldg(&bi4[lane + 32]);
    float4 v0o, v1o;
    v0o.x = fmaxf(fmaf(acc0.x, r_lo, bb0.x), 0.f);
    v0o.y = fmaxf(fmaf(acc0.y, r_lo, bb0.y), 0.f);
    v0o.z = fmaxf(fmaf(acc0.z, r_lo, bb0.z), 0.f);
    v0o.w = fmaxf(fmaf(acc0.w, r_lo, bb0.w), 0.f);
    v1o.x = fmaxf(fmaf(acc1.x, r_hi, bb1.x), 0.f);
    v1o.y = fmaxf(fmaf(acc1.y, r_hi, bb1.y), 0.f);
    v1o.z = fmaxf(fmaf(acc1.z, r_hi, bb1.z), 0.f);
    v1o.w = fmaxf(fmaf(acc1.w, r_hi, bb1.w), 0.f);
    float4* xo = (float4*)(xout + (size_t)w * HF);
    xo[lane]      = v0o;
    xo[lane + 32] = v1o;
}

// ---------------- generic tiled SGEMM for the small tail GEMMs ----------------
template<int BM, int BN, int BK, int TM, int TN, int NT>
__global__ void sgemm_tn(const float* __restrict__ A, const float* __restrict__ B,
                         const float* __restrict__ bias, float* __restrict__ C,
                         int M, int N, int K)
{
    __shared__ float As[BK][BM];
    __shared__ float Bs[BK][BN];
    int tid = threadIdx.x;
    int tx = tid % (BN / TN);
    int ty = tid / (BN / TN);
    int m0 = blockIdx.x * BM;
    int n0 = blockIdx.y * BN;

    float acc[TM][TN];
    #pragma unroll
    for (int i = 0; i < TM; i++)
        #pragma unroll
        for (int j = 0; j < TN; j++) acc[i][j] = 0.f;

    for (int k0 = 0; k0 < K; k0 += BK) {
        for (int li = tid; li < BM * BK / 4; li += NT) {
            int r  = li / (BK / 4);
            int c4 = li % (BK / 4);
            float4 v = make_float4(0.f, 0.f, 0.f, 0.f);
            if (m0 + r < M)
                v = *(const float4*)&A[(size_t)(m0 + r) * K + k0 + c4 * 4];
            As[c4 * 4 + 0][r] = v.x;
            As[c4 * 4 + 1][r] = v.y;
            As[c4 * 4 + 2][r] = v.z;
            As[c4 * 4 + 3][r] = v.w;
        }
        for (int li = tid; li < BN * BK / 4; li += NT) {
            int r  = li / (BK / 4);
            int c4 = li % (BK / 4);
            float4 v = *(const float4*)&B[(size_t)(n0 + r) * K + k0 + c4 * 4];
            Bs[c4 * 4 + 0][r] = v.x;
            Bs[c4 * 4 + 1][r] = v.y;
            Bs[c4 * 4 + 2][r] = v.z;
            Bs[c4 * 4 + 3][r] = v.w;
        }
        __syncthreads();
        #pragma unroll
        for (int k = 0; k < BK; k++) {
            float a[TM], b[TN];
            #pragma unroll
            for (int i = 0; i < TM; i++) a[i] = As[k][ty * TM + i];
            #pragma unroll
            for (int j = 0; j < TN; j++) b[j] = Bs[k][tx * TN + j];
            #pragma unroll
            for (int i = 0; i < TM; i++)
                #pragma unroll
                for (int j = 0; j < TN; j++)
                    acc[i][j] = fmaf(a[i], b[j], acc[i][j]);
        }
        __syncthreads();
    }

    #pragma unroll
    for (int i = 0; i < TM; i++) {
        int row = m0 + ty * TM + i;
        if (row >= M) continue;
        #pragma unroll
        for (int j = 0; j < TN; j++) {
            int col = n0 + tx * TN + j;
            float v = acc[i][j];
            if (bias) v += bias[col];
            C[(size_t)row * N + col] = v;
        }
    }
}

// ---------------- launch ----------------
extern "C" void kernel_launch(void* const* d_in, const int* in_sizes, int n_in,
                              void* d_out, int out_size)
{
    const float* sfeat = (const float*)d_in[0];
    const float* bfeat = (const float*)d_in[1];
    const float* smask = (const float*)d_in[2];
    const float* bmask = (const float*)d_in[3];
    const int*   ei    = (const int*)  d_in[4];
    const int*   batch = (const int*)  d_in[5];
    const float* sW    = (const float*)d_in[6];
    const float* sb    = (const float*)d_in[7];
    const float* bW    = (const float*)d_in[8];
    const float* bb    = (const float*)d_in[9];
    const float* W[3]  = {(const float*)d_in[10], (const float*)d_in[14], (const float*)d_in[18]};
    const float* asr[3]= {(const float*)d_in[11], (const float*)d_in[15], (const float*)d_in[19]};
    const float* ads[3]= {(const float*)d_in[12], (const float*)d_in[16], (const float*)d_in[20]};
    const float* bl[3] = {(const float*)d_in[13], (const float*)d_in[17], (const float*)d_in[21]};
    const float* aggW  = (const float*)d_in[22];
    const float* aggb  = (const float*)d_in[23];
    const float* muW   = (const float*)d_in[24];
    const float* mub   = (const float*)d_in[25];
    const float* varW  = (const float*)d_in[26];
    const float* varb  = (const float*)d_in[27];
    float* out = (float*)d_out;

    float *px, *ph, *pn0, *pg, *plat;
    cudaGetSymbolAddress((void**)&px,   d_x);
    cudaGetSymbolAddress((void**)&ph,   d_h);
    cudaGetSymbolAddress((void**)&pn0,  d_n0);
    cudaGetSymbolAddress((void**)&pg,   d_g);
    cudaGetSymbolAddress((void**)&plat, d_lat);

    // zero + CSR build (reused across layers)
    zero_kernel<<<(NGR * GCOLS + 255) / 256, 256>>>();
    count_deg_kernel<<<(EE_TOT + 255) / 256, 256>>>(ei);
    scan_deg_kernel<<<1, 1024>>>();
    scatter_csr_kernel<<<(EE_TOT + 255) / 256, 256>>>(ei);

    node_init_kernel<<<N_NODES / 16, 256>>>(sfeat, bfeat, smask, bmask, sW, sb, bW, bb);
    pool_max_kernel<<<(N_NODES + 63) / 64, FDIM>>>(pn0, batch, FDIM, 0);

    for (int l = 0; l < 3; l++) {
        const float* xin = (l == 0) ? pn0 : px;
        int Kin = (l == 0) ? FDIM : HF;
        dim3 gg((N_NODES + 127) / 128, HF / 128);
        sgemm_attn<<<gg, 256>>>(xin, W[l], ph, N_NODES, Kin, asr[l], ads[l]);
        csr_attn_agg_kernel<<<(N_NODES + 7) / 8, 256>>>(ph, bl[l], px);
        pool_max_kernel<<<(N_NODES + 63) / 64, HF>>>(px, batch, HF, FDIM + l * HF);
    }

    // g [64,832] -> latent [64,512] -> mu / log_var [64,512]
    dim3 gl((NGR + 15) / 16, LATD / 64);
    sgemm_tn<16, 64, 16, 2, 4, 128><<<gl, 128>>>(pg,   aggW, aggb, plat, NGR, LATD, GCOLS);
    sgemm_tn<16, 64, 16, 2, 4, 128><<<gl, 128>>>(plat, muW,  mub,  out,              NGR, LATD, LATD);
    sgemm_tn<16, 64, 16, 2, 4, 128><<<gl, 128>>>(plat, varW, varb, out + NGR * LATD, NGR, LATD, LATD);
}

// round 9
// speedup vs baseline: 1.5784x; 1.1103x over previous
#include <cuda_runtime.h>
#include <cuda_bf16.h>
#include <math.h>

// Problem constants
#define N_NODES 20000
#define N_EDGES 320000
#define EE_TOT  (N_EDGES + N_NODES)   // with self loops
#define FDIM    64
#define NHEAD   4
#define HF      256                   // NHEAD * FDIM
#define NGR     64
#define LATD    512
#define GCOLS   832                   // FDIM * (1 + 3*NHEAD)

#define W_ELEMS (HF*FDIM + 2*HF*HF)   // 147456
#define W_OFF2  (HF*FDIM)             // 16384
#define W_OFF3  (HF*FDIM + HF*HF)     // 81920

// -------- scratch (static device globals; no allocation allowed) --------
static __device__ __align__(16) float d_n0 [N_NODES * FDIM];
static __device__ __align__(16) float d_x  [N_NODES * HF];
static __device__ __align__(16) float d_h  [N_NODES * HF];
static __device__ __align__(16) float d_s  [N_NODES * NHEAD];
static __device__ __align__(16) float d_dt [N_NODES * NHEAD];
static __device__ __align__(16) float d_g  [NGR * GCOLS];
static __device__ __align__(16) float d_lat[NGR * LATD];
// bf16 split operands for tensor-core GEMM
static __device__ __align__(16) __nv_bfloat16 d_n0h[N_NODES * FDIM];
static __device__ __align__(16) __nv_bfloat16 d_n0l[N_NODES * FDIM];
static __device__ __align__(16) __nv_bfloat16 d_xh [N_NODES * HF];
static __device__ __align__(16) __nv_bfloat16 d_xl [N_NODES * HF];
static __device__ __align__(16) __nv_bfloat16 d_Wh [W_ELEMS];
static __device__ __align__(16) __nv_bfloat16 d_Wl [W_ELEMS];
// CSR (built per launch, reused by all 3 layers)
static __device__ int d_deg  [N_NODES + 1];
static __device__ int d_start[N_NODES + 1];
static __device__ int d_fill [N_NODES];
static __device__ int d_csrc [EE_TOT];

__device__ __forceinline__ float lrelu(float x) { return x > 0.f ? x : 0.2f * x; }

__device__ __forceinline__ unsigned s2u(const void* p) {
    return (unsigned)__cvta_generic_to_shared(p);
}

#define CPA16(dst, src, sz) \
    asm volatile("cp.async.ca.shared.global [%0], [%1], 16, %2;" \
                 :: "r"(dst), "l"(src), "r"(sz))
#define CPA_COMMIT() asm volatile("cp.async.commit_group;")
#define CPA_WAIT(n)  asm volatile("cp.async.wait_group %0;" :: "n"(n) : "memory")

#define LDSM4(R, p) \
    asm volatile("ldmatrix.sync.aligned.m8n8.x4.shared.b16 {%0,%1,%2,%3}, [%4];" \
                 : "=r"((R)[0]), "=r"((R)[1]), "=r"((R)[2]), "=r"((R)[3]) : "r"(p))

#define MMA16816(D, A, B0, B1) \
    asm volatile("mma.sync.aligned.m16n8k16.row.col.f32.bf16.bf16.f32 " \
                 "{%0,%1,%2,%3}, {%4,%5,%6,%7}, {%8,%9}, {%0,%1,%2,%3};" \
                 : "+f"((D)[0]), "+f"((D)[1]), "+f"((D)[2]), "+f"((D)[3]) \
                 : "r"((A)[0]), "r"((A)[1]), "r"((A)[2]), "r"((A)[3]), \
                   "r"(B0), "r"(B1))

// ---------------- zero pass: g buffer + CSR counters ----------------
__global__ void zero_kernel() {
    int i = blockIdx.x * blockDim.x + threadIdx.x;
    if (i < NGR * GCOLS) d_g[i] = 0.f;
    if (i <= N_NODES)    d_deg[i] = 0;
    if (i < N_NODES)     d_fill[i] = 0;
}

// ---------------- weight split fp32 -> bf16 hi/lo ----------------
__global__ void conv_w_kernel(const float* __restrict__ W1,
                              const float* __restrict__ W2,
                              const float* __restrict__ W3)
{
    int i = blockIdx.x * blockDim.x + threadIdx.x;
    if (i >= W_ELEMS) return;
    float v;
    if (i < W_OFF2)      v = W1[i];
    else if (i < W_OFF3) v = W2[i - W_OFF2];
    else                 v = W3[i - W_OFF3];
    __nv_bfloat16 h = __float2bfloat16(v);
    d_Wh[i] = h;
    d_Wl[i] = __float2bfloat16(v - __bfloat162float(h));
}

// ---------------- CSR build ----------------
__global__ void count_deg_kernel(const int* __restrict__ ei) {
    int i = blockIdx.x * blockDim.x + threadIdx.x;
    if (i >= EE_TOT) return;
    int d = (i < N_EDGES) ? ei[N_EDGES + i] : (i - N_EDGES);
    atomicAdd(&d_deg[d], 1);
}

__global__ void scan_deg_kernel() {
    __shared__ int partial[1024];
    int t = threadIdx.x;
    const int CH = (N_NODES + 1023) / 1024;   // 20
    int b0 = t * CH;
    int bend = min(b0 + CH, N_NODES);
    int sum = 0;
    for (int i = b0; i < bend; i++) sum += d_deg[i];
    partial[t] = sum;
    __syncthreads();
    for (int off = 1; off < 1024; off <<= 1) {
        int v = (t >= off) ? partial[t - off] : 0;
        __syncthreads();
        partial[t] += v;
        __syncthreads();
    }
    int run = (t == 0) ? 0 : partial[t - 1];
    for (int i = b0; i < bend; i++) {
        d_start[i] = run;
        run += d_deg[i];
    }
    if (t == 1023) d_start[N_NODES] = run;
}

__global__ void scatter_csr_kernel(const int* __restrict__ ei) {
    int i = blockIdx.x * blockDim.x + threadIdx.x;
    if (i >= EE_TOT) return;
    int s, d;
    if (i < N_EDGES) { s = ei[i]; d = ei[N_EDGES + i]; }
    else             { s = d = i - N_EDGES; }
    int slot = atomicAdd(&d_fill[d], 1);
    d_csrc[d_start[d] + slot] = s;
}

// ---------------- node feature encoders + mask mix (+bf16 split out) ----------------
__global__ void node_init_kernel(const float* __restrict__ sfeat,
                                 const float* __restrict__ bfeat,
                                 const float* __restrict__ smask,
                                 const float* __restrict__ bmask,
                                 const float* __restrict__ sW,
                                 const float* __restrict__ sb,
                                 const float* __restrict__ bW,
                                 const float* __restrict__ bb)
{
    __shared__ float sWs[128 * 65];   // [k][f], padded stride 65
    __shared__ float xs[4 * 128];
    int tid = threadIdx.x;
    for (int li = tid; li < 64 * 128; li += 256) {
        int f = li >> 7;
        int k = li & 127;
        sWs[k * 65 + f] = sW[li];     // sW row-major [64,128]
    }
    __syncthreads();

    int nb0 = blockIdx.x * 16;
    for (int grp = 0; grp < 4; grp++) {
        int nb = nb0 + grp * 4;
        xs[tid]       = sfeat[nb * 128 + tid];
        xs[tid + 256] = sfeat[nb * 128 + tid + 256];
        __syncthreads();
        int ni = tid >> 6;
        int f  = tid & 63;
        int n  = nb + ni;
        float acc = sb[f];
        #pragma unroll 8
        for (int k = 0; k < 128; k++)
            acc = fmaf(xs[ni * 128 + k], sWs[k * 65 + f], acc);
        float sv = fmaxf(acc, 0.f);
        float bacc = bb[f];
        #pragma unroll
        for (int k = 0; k < 5; k++)
            bacc = fmaf(bfeat[n * 5 + k], bW[f * 5 + k], bacc);
        float bv = fmaxf(bacc, 0.f);
        float v = sv * smask[n] + bv * bmask[n];
        d_n0[n * FDIM + f] = v;
        __nv_bfloat16 hb = __float2bfloat16(v);
        d_n0h[n * FDIM + f] = hb;
        d_n0l[n * FDIM + f] = __float2bfloat16(v - __bfloat162float(hb));
        __syncthreads();
    }
}

// ---------------- segment-max pooling, block-local reduction ----------------
__global__ void pool_max_kernel(const float* __restrict__ x,
                                const int* __restrict__ batch,
                                int cols, int goff)
{
    int t = threadIdx.x;
    int n0 = blockIdx.x * 64;
    int nend = min(n0 + 64, N_NODES);
    int curg = batch[n0];
    float mx = 0.f;                       // values are >= 0 (post-relu)
    for (int n = n0; n < nend; n++) {
        int g = batch[n];
        if (g != curg) {
            atomicMax((int*)&d_g[curg * GCOLS + goff + t], __float_as_int(mx));
            curg = g;
            mx = 0.f;
        }
        mx = fmaxf(mx, x[(size_t)n * cols + t]);
    }
    atomicMax((int*)&d_g[curg * GCOLS + goff + t], __float_as_int(mx));
}

// ---------------- tensor-core h-GEMM (bf16 split, fp32 accuracy) ----------------
// C[M,HF] = A[M,K] @ B[HF,K]^T via 3-term bf16 MMA; fused attn-score epilogue.
// CTA tile 128x128, 8 warps (4x2 of 32x64), K-tile 16, 2-stage cp.async pipeline.
#define SM_STRIDE 24   // bf16 elems per smem row (16+8 pad): 48B, 16B-aligned rows
__global__ __launch_bounds__(256)
void mma_gemm_attn(const __nv_bfloat16* __restrict__ Ah, const __nv_bfloat16* __restrict__ Al,
                   const __nv_bfloat16* __restrict__ Bh, const __nv_bfloat16* __restrict__ Bl,
                   float* __restrict__ C, int M, int K,
                   const float* __restrict__ asrc, const float* __restrict__ adst)
{
    // [stage][buf: Ah,Al,Bh,Bl][128*24]
    __shared__ __nv_bfloat16 sm[2][4][128 * SM_STRIDE];

    const int tid  = threadIdx.x;
    const int lane = tid & 31;
    const int warp = tid >> 5;
    const int wx   = warp >> 1;          // 0..3 -> m offset wx*32
    const int wy   = warp & 1;           // 0..1 -> n offset wy*64 (== one head)
    const int m0   = blockIdx.x * 128;
    const int n0   = blockIdx.y * 128;

    float acc[2][8][4];
    #pragma unroll
    for (int mi = 0; mi < 2; mi++)
        #pragma unroll
        for (int ni = 0; ni < 8; ni++)
            #pragma unroll
            for (int q = 0; q < 4; q++) acc[mi][ni][q] = 0.f;

    // per-thread load slot: 256 threads cover 128 rows x 2 16B-segments per buffer
    const int lr  = tid >> 1;            // row 0..127
    const int lsg = (tid & 1) * 8;       // bf16 offset 0 or 8
    const int szA = (m0 + lr < M) ? 16 : 0;
    const size_t aoffBase = (size_t)(m0 + lr) * K + lsg;
    const size_t boffBase = (size_t)(n0 + lr) * K + lsg;
    const unsigned dstOff = lr * SM_STRIDE + lsg;

    // ldmatrix thread addressing
    const int arow  = wx * 32 + (lane & 15);
    const int acol8 = (lane >> 4) * 8;
    const int bn    = wy * 64 + (lane & 7) + ((lane >> 4) << 3);
    const int bk8   = ((lane >> 3) & 1) * 8;

    const int nt = K >> 4;   // number of 16-wide k tiles

    // prologue: stage 0
    {
        CPA16(s2u(&sm[0][0][dstOff]), Ah + aoffBase, szA);
        CPA16(s2u(&sm[0][1][dstOff]), Al + aoffBase, szA);
        CPA16(s2u(&sm[0][2][dstOff]), Bh + boffBase, 16);
        CPA16(s2u(&sm[0][3][dstOff]), Bl + boffBase, 16);
        CPA_COMMIT();
    }

    for (int kt = 0; kt < nt; kt++) {
        int st = kt & 1;
        if (kt + 1 < nt) {
            int sn = st ^ 1;
            size_t ka = (size_t)(kt + 1) * 16;
            CPA16(s2u(&sm[sn][0][dstOff]), Ah + aoffBase + ka, szA);
            CPA16(s2u(&sm[sn][1][dstOff]), Al + aoffBase + ka, szA);
            CPA16(s2u(&sm[sn][2][dstOff]), Bh + boffBase + ka, 16);
            CPA16(s2u(&sm[sn][3][dstOff]), Bl + boffBase + ka, 16);
            CPA_COMMIT();
            CPA_WAIT(1);
        } else {
            CPA_WAIT(0);
        }
        __syncthreads();

        const __nv_bfloat16* pAh = sm[st][0];
        const __nv_bfloat16* pAl = sm[st][1];
        const __nv_bfloat16* pBh = sm[st][2];
        const __nv_bfloat16* pBl = sm[st][3];

        unsigned ah[2][4], al[2][4], bh[4][4], bl[4][4];
        #pragma unroll
        for (int mi = 0; mi < 2; mi++) {
            LDSM4(ah[mi], s2u(&pAh[(arow + mi * 16) * SM_STRIDE + acol8]));
            LDSM4(al[mi], s2u(&pAl[(arow + mi * 16) * SM_STRIDE + acol8]));
        }
        #pragma unroll
        for (int p = 0; p < 4; p++) {
            LDSM4(bh[p], s2u(&pBh[(bn + p * 16) * SM_STRIDE + bk8]));
            LDSM4(bl[p], s2u(&pBl[(bn + p * 16) * SM_STRIDE + bk8]));
        }
        #pragma unroll
        for (int mi = 0; mi < 2; mi++)
            #pragma unroll
            for (int ni = 0; ni < 8; ni++) {
                int p = ni >> 1, o = (ni & 1) * 2;
                MMA16816(acc[mi][ni], ah[mi], bh[p][o], bh[p][o + 1]);
                MMA16816(acc[mi][ni], ah[mi], bl[p][o], bl[p][o + 1]);
                MMA16816(acc[mi][ni], al[mi], bh[p][o], bh[p][o + 1]);
            }
        __syncthreads();
    }

    // ---- epilogue: store C (h) ----
    const int rbase = m0 + wx * 32 + (lane >> 2);
    const int cbase = n0 + wy * 64 + (lane & 3) * 2;
    #pragma unroll
    for (int mi = 0; mi < 2; mi++) {
        #pragma unroll
        for (int ni = 0; ni < 8; ni++) {
            int row = rbase + mi * 16;
            int col = cbase + ni * 8;
            if (row < M)
                *(float2*)&C[(size_t)row * HF + col] = make_float2(acc[mi][ni][0], acc[mi][ni][1]);
            if (row + 8 < M)
                *(float2*)&C[(size_t)(row + 8) * HF + col] = make_float2(acc[mi][ni][2], acc[mi][ni][3]);
        }
    }

    // ---- epilogue: attention scores (this warp's 64 cols == one full head) ----
    const int head = (n0 >> 6) + wy;
    float2 av[8], dvv[8];
    #pragma unroll
    for (int ni = 0; ni < 8; ni++) {
        av[ni]  = *(const float2*)&asrc[head * 64 + ni * 8 + (lane & 3) * 2];
        dvv[ni] = *(const float2*)&adst[head * 64 + ni * 8 + (lane & 3) * 2];
    }
    #pragma unroll
    for (int mi = 0; mi < 2; mi++) {
        float p0s = 0.f, p0d = 0.f, p1s = 0.f, p1d = 0.f;
        #pragma unroll
        for (int ni = 0; ni < 8; ni++) {
            p0s += acc[mi][ni][0] * av[ni].x  + acc[mi][ni][1] * av[ni].y;
            p0d += acc[mi][ni][0] * dvv[ni].x + acc[mi][ni][1] * dvv[ni].y;
            p1s += acc[mi][ni][2] * av[ni].x  + acc[mi][ni][3] * av[ni].y;
            p1d += acc[mi][ni][2] * dvv[ni].x + acc[mi][ni][3] * dvv[ni].y;
        }
        #pragma unroll
        for (int off = 1; off <= 2; off <<= 1) {
            p0s += __shfl_xor_sync(0xFFFFFFFFu, p0s, off);
            p0d += __shfl_xor_sync(0xFFFFFFFFu, p0d, off);
            p1s += __shfl_xor_sync(0xFFFFFFFFu, p1s, off);
            p1d += __shfl_xor_sync(0xFFFFFFFFu, p1d, off);
        }
        if ((lane & 3) == 0) {
            int row = rbase + mi * 16;
            if (row < M)     { d_s[row * 4 + head] = p0s; d_dt[row * 4 + head] = p0d; }
            if (row + 8 < M) { d_s[(row + 8) * 4 + head] = p1s; d_dt[(row + 8) * 4 + head] = p1d; }
        }
    }
}

// ---------------- fused softmax + aggregation (warp per dst node) ----------------
__device__ __forceinline__ void split_store4(__nv_bfloat16* XH, __nv_bfloat16* XL,
                                             size_t off, float4 v) {
    __nv_bfloat162 h0 = __floats2bfloat162_rn(v.x, v.y);
    __nv_bfloat162 h1 = __floats2bfloat162_rn(v.z, v.w);
    __nv_bfloat162 l0 = __floats2bfloat162_rn(v.x - __low2float(h0), v.y - __high2float(h0));
    __nv_bfloat162 l1 = __floats2bfloat162_rn(v.z - __low2float(h1), v.w - __high2float(h1));
    uint2 uh, ul;
    uh.x = reinterpret_cast<unsigned&>(h0); uh.y = reinterpret_cast<unsigned&>(h1);
    ul.x = reinterpret_cast<unsigned&>(l0); ul.y = reinterpret_cast<unsigned&>(l1);
    *(uint2*)(XH + off) = uh;
    *(uint2*)(XL + off) = ul;
}

__global__ void csr_attn_agg_kernel(const float* __restrict__ h,
                                    const float* __restrict__ bias,
                                    float* __restrict__ xout)
{
    __shared__ float4 sEx[8][64];
    int warp = threadIdx.x >> 5;
    int lane = threadIdx.x & 31;
    int w = blockIdx.x * 8 + warp;
    if (w >= N_NODES) return;
    int js = d_start[w], je = d_start[w + 1];
    int deg = je - js;
    float4 dv = *(const float4*)&d_dt[w * 4];

    // ---- pass 1: logits in registers (deg<=64 common case), running max ----
    float4 e0 = make_float4(0.f, 0.f, 0.f, 0.f);
    float4 e1 = make_float4(0.f, 0.f, 0.f, 0.f);
    float m0 = -INFINITY, m1 = -INFINITY, m2 = -INFINITY, m3 = -INFINITY;
    int j0 = js + lane;
    bool v0 = j0 < je;
    bool v1 = j0 + 32 < je;
    if (v0) {
        int s = d_csrc[j0];
        float4 sv = __ldg((const float4*)&d_s[s * 4]);
        e0.x = lrelu(sv.x + dv.x); e0.y = lrelu(sv.y + dv.y);
        e0.z = lrelu(sv.z + dv.z); e0.w = lrelu(sv.w + dv.w);
        m0 = e0.x; m1 = e0.y; m2 = e0.z; m3 = e0.w;
    }
    if (v1) {
        int s = d_csrc[j0 + 32];
        float4 sv = __ldg((const float4*)&d_s[s * 4]);
        e1.x = lrelu(sv.x + dv.x); e1.y = lrelu(sv.y + dv.y);
        e1.z = lrelu(sv.z + dv.z); e1.w = lrelu(sv.w + dv.w);
        m0 = fmaxf(m0, e1.x); m1 = fmaxf(m1, e1.y);
        m2 = fmaxf(m2, e1.z); m3 = fmaxf(m3, e1.w);
    }
    for (int j = j0 + 64; j < je; j += 32) {     // rare (deg > 64)
        int s = d_csrc[j];
        float4 sv = __ldg((const float4*)&d_s[s * 4]);
        m0 = fmaxf(m0, lrelu(sv.x + dv.x)); m1 = fmaxf(m1, lrelu(sv.y + dv.y));
        m2 = fmaxf(m2, lrelu(sv.z + dv.z)); m3 = fmaxf(m3, lrelu(sv.w + dv.w));
    }
    #pragma unroll
    for (int off = 16; off > 0; off >>= 1) {
        m0 = fmaxf(m0, __shfl_xor_sync(0xFFFFFFFFu, m0, off));
        m1 = fmaxf(m1, __shfl_xor_sync(0xFFFFFFFFu, m1, off));
        m2 = fmaxf(m2, __shfl_xor_sync(0xFFFFFFFFu, m2, off));
        m3 = fmaxf(m3, __shfl_xor_sync(0xFFFFFFFFu, m3, off));
    }

    // ---- pass 2: exp + sum ----
    float s0 = 0.f, s1 = 0.f, s2 = 0.f, s3 = 0.f;
    if (v0) {
        e0.x = __expf(e0.x - m0); e0.y = __expf(e0.y - m1);
        e0.z = __expf(e0.z - m2); e0.w = __expf(e0.w - m3);
        s0 += e0.x; s1 += e0.y; s2 += e0.z; s3 += e0.w;
    }
    if (v1) {
        e1.x = __expf(e1.x - m0); e1.y = __expf(e1.y - m1);
        e1.z = __expf(e1.z - m2); e1.w = __expf(e1.w - m3);
        s0 += e1.x; s1 += e1.y; s2 += e1.z; s3 += e1.w;
    }
    for (int j = j0 + 64; j < je; j += 32) {     // rare
        int s = d_csrc[j];
        float4 sv = __ldg((const float4*)&d_s[s * 4]);
        s0 += __expf(lrelu(sv.x + dv.x) - m0);
        s1 += __expf(lrelu(sv.y + dv.y) - m1);
        s2 += __expf(lrelu(sv.z + dv.z) - m2);
        s3 += __expf(lrelu(sv.w + dv.w) - m3);
    }
    #pragma unroll
    for (int off = 16; off > 0; off >>= 1) {
        s0 += __shfl_xor_sync(0xFFFFFFFFu, s0, off);
        s1 += __shfl_xor_sync(0xFFFFFFFFu, s1, off);
        s2 += __shfl_xor_sync(0xFFFFFFFFu, s2, off);
        s3 += __shfl_xor_sync(0xFFFFFFFFu, s3, off);
    }
    float4 rinv = make_float4(1.f / s0, 1.f / s1, 1.f / s2, 1.f / s3);

    sEx[warp][lane]      = e0;
    sEx[warp][lane + 32] = e1;
    __syncwarp();

    // ---- pass 3: weighted gather ----
    float4 acc0 = make_float4(0.f, 0.f, 0.f, 0.f);
    float4 acc1 = make_float4(0.f, 0.f, 0.f, 0.f);
    bool lo = lane < 16;
    for (int jj = 0; jj < deg; jj++) {
        float4 a4;
        if (jj < 64) {
            a4 = sEx[warp][jj];
        } else {                                   // rare fallback: recompute
            int s = d_csrc[js + jj];
            float4 sv = __ldg((const float4*)&d_s[s * 4]);
            a4.x = __expf(lrelu(sv.x + dv.x) - m0);
            a4.y = __expf(lrelu(sv.y + dv.y) - m1);
            a4.z = __expf(lrelu(sv.z + dv.z) - m2);
            a4.w = __expf(lrelu(sv.w + dv.w) - m3);
        }
        int src = d_csrc[js + jj];
        float a_lo = lo ? a4.x : a4.y;
        float a_hi = lo ? a4.z : a4.w;
        const float4* hp4 = (const float4*)(h + (size_t)src * HF);
        float4 h0 = __ldg(&hp4[lane]);
        float4 h1 = __ldg(&hp4[lane + 32]);
        acc0.x = fmaf(a_lo, h0.x, acc0.x);
        acc0.y = fmaf(a_lo, h0.y, acc0.y);
        acc0.z = fmaf(a_lo, h0.z, acc0.z);
        acc0.w = fmaf(a_lo, h0.w, acc0.w);
        acc1.x = fmaf(a_hi, h1.x, acc1.x);
        acc1.y = fmaf(a_hi, h1.y, acc1.y);
        acc1.z = fmaf(a_hi, h1.z, acc1.z);
        acc1.w = fmaf(a_hi, h1.w, acc1.w);
    }

    float r_lo = lo ? rinv.x : rinv.y;
    float r_hi = lo ? rinv.z : rinv.w;
    const float4* bi4 = (const float4*)bias;
    float4 bb0 = __ldg(&bi4[lane]);
    float4 bb1 = __ldg(&bi4[lane + 32]);
    float4 v0o, v1o;
    v0o.x = fmaxf(fmaf(acc0.x, r_lo, bb0.x), 0.f);
    v0o.y = fmaxf(fmaf(acc0.y, r_lo, bb0.y), 0.f);
    v0o.z = fmaxf(fmaf(acc0.z, r_lo, bb0.z), 0.f);
    v0o.w = fmaxf(fmaf(acc0.w, r_lo, bb0.w), 0.f);
    v1o.x = fmaxf(fmaf(acc1.x, r_hi, bb1.x), 0.f);
    v1o.y = fmaxf(fmaf(acc1.y, r_hi, bb1.y), 0.f);
    v1o.z = fmaxf(fmaf(acc1.z, r_hi, bb1.z), 0.f);
    v1o.w = fmaxf(fmaf(acc1.w, r_hi, bb1.w), 0.f);
    float4* xo = (float4*)(xout + (size_t)w * HF);
    xo[lane]      = v0o;
    xo[lane + 32] = v1o;
    // bf16 split for next layer's tensor-core GEMM
    split_store4(d_xh, d_xl, (size_t)w * HF + lane * 4,        v0o);
    split_store4(d_xh, d_xl, (size_t)w * HF + (lane + 32) * 4, v1o);
}

// ---------------- generic tiled SGEMM for the small tail GEMMs ----------------
template<int BM, int BN, int BK, int TM, int TN, int NT>
__global__ void sgemm_tn(const float* __restrict__ A, const float* __restrict__ B,
                         const float* __restrict__ bias, float* __restrict__ C,
                         int M, int N, int K)
{
    __shared__ float As[BK][BM];
    __shared__ float Bs[BK][BN];
    int tid = threadIdx.x;
    int tx = tid % (BN / TN);
    int ty = tid / (BN / TN);
    int m0 = blockIdx.x * BM;
    int n0 = blockIdx.y * BN;

    float acc[TM][TN];
    #pragma unroll
    for (int i = 0; i < TM; i++)
        #pragma unroll
        for (int j = 0; j < TN; j++) acc[i][j] = 0.f;

    for (int k0 = 0; k0 < K; k0 += BK) {
        for (int li = tid; li < BM * BK / 4; li += NT) {
            int r  = li / (BK / 4);
            int c4 = li % (BK / 4);
            float4 v = make_float4(0.f, 0.f, 0.f, 0.f);
            if (m0 + r < M)
                v = *(const float4*)&A[(size_t)(m0 + r) * K + k0 + c4 * 4];
            As[c4 * 4 + 0][r] = v.x;
            As[c4 * 4 + 1][r] = v.y;
            As[c4 * 4 + 2][r] = v.z;
            As[c4 * 4 + 3][r] = v.w;
        }
        for (int li = tid; li < BN * BK / 4; li += NT) {
            int r  = li / (BK / 4);
            int c4 = li % (BK / 4);
            float4 v = *(const float4*)&B[(size_t)(n0 + r) * K + k0 + c4 * 4];
            Bs[c4 * 4 + 0][r] = v.x;
            Bs[c4 * 4 + 1][r] = v.y;
            Bs[c4 * 4 + 2][r] = v.z;
            Bs[c4 * 4 + 3][r] = v.w;
        }
        __syncthreads();
        #pragma unroll
        for (int k = 0; k < BK; k++) {
            float a[TM], b[TN];
            #pragma unroll
            for (int i = 0; i < TM; i++) a[i] = As[k][ty * TM + i];
            #pragma unroll
            for (int j = 0; j < TN; j++) b[j] = Bs[k][tx * TN + j];
            #pragma unroll
            for (int i = 0; i < TM; i++)
                #pragma unroll
                for (int j = 0; j < TN; j++)
                    acc[i][j] = fmaf(a[i], b[j], acc[i][j]);
        }
        __syncthreads();
    }

    #pragma unroll
    for (int i = 0; i < TM; i++) {
        int row = m0 + ty * TM + i;
        if (row >= M) continue;
        #pragma unroll
        for (int j = 0; j < TN; j++) {
            int col = n0 + tx * TN + j;
            float v = acc[i][j];
            if (bias) v += bias[col];
            C[(size_t)row * N + col] = v;
        }
    }
}

// ---------------- launch ----------------
extern "C" void kernel_launch(void* const* d_in, const int* in_sizes, int n_in,
                              void* d_out, int out_size)
{
    const float* sfeat = (const float*)d_in[0];
    const float* bfeat = (const float*)d_in[1];
    const float* smask = (const float*)d_in[2];
    const float* bmask = (const float*)d_in[3];
    const int*   ei    = (const int*)  d_in[4];
    const int*   batch = (const int*)  d_in[5];
    const float* sW    = (const float*)d_in[6];
    const float* sb    = (const float*)d_in[7];
    const float* bW    = (const float*)d_in[8];
    const float* bb    = (const float*)d_in[9];
    const float* W[3]  = {(const float*)d_in[10], (const float*)d_in[14], (const float*)d_in[18]};
    const float* asr[3]= {(const float*)d_in[11], (const float*)d_in[15], (const float*)d_in[19]};
    const float* ads[3]= {(const float*)d_in[12], (const float*)d_in[16], (const float*)d_in[20]};
    const float* bl[3] = {(const float*)d_in[13], (const float*)d_in[17], (const float*)d_in[21]};
    const float* aggW  = (const float*)d_in[22];
    const float* aggb  = (const float*)d_in[23];
    const float* muW   = (const float*)d_in[24];
    const float* mub   = (const float*)d_in[25];
    const float* varW  = (const float*)d_in[26];
    const float* varb  = (const float*)d_in[27];
    float* out = (float*)d_out;

    float *px, *ph, *pn0, *pg, *plat;
    __nv_bfloat16 *pn0h, *pn0l, *pxh, *pxl, *pWh, *pWl;
    cudaGetSymbolAddress((void**)&px,   d_x);
    cudaGetSymbolAddress((void**)&ph,   d_h);
    cudaGetSymbolAddress((void**)&pn0,  d_n0);
    cudaGetSymbolAddress((void**)&pg,   d_g);
    cudaGetSymbolAddress((void**)&plat, d_lat);
    cudaGetSymbolAddress((void**)&pn0h, d_n0h);
    cudaGetSymbolAddress((void**)&pn0l, d_n0l);
    cudaGetSymbolAddress((void**)&pxh,  d_xh);
    cudaGetSymbolAddress((void**)&pxl,  d_xl);
    cudaGetSymbolAddress((void**)&pWh,  d_Wh);
    cudaGetSymbolAddress((void**)&pWl,  d_Wl);

    const int woff[3] = {0, W_OFF2, W_OFF3};

    // zero + weight conversion + CSR build (reused across layers)
    zero_kernel<<<(NGR * GCOLS + 255) / 256, 256>>>();
    conv_w_kernel<<<(W_ELEMS + 255) / 256, 256>>>(W[0], W[1], W[2]);
    count_deg_kernel<<<(EE_TOT + 255) / 256, 256>>>(ei);
    scan_deg_kernel<<<1, 1024>>>();
    scatter_csr_kernel<<<(EE_TOT + 255) / 256, 256>>>(ei);

    node_init_kernel<<<N_NODES / 16, 256>>>(sfeat, bfeat, smask, bmask, sW, sb, bW, bb);
    pool_max_kernel<<<(N_NODES + 63) / 64, FDIM>>>(pn0, batch, FDIM, 0);

    for (int l = 0; l < 3; l++) {
        const __nv_bfloat16* Ah = (l == 0) ? pn0h : pxh;
        const __nv_bfloat16* Al = (l == 0) ? pn0l : pxl;
        int Kin = (l == 0) ? FDIM : HF;
        dim3 gg((N_NODES + 127) / 128, HF / 128);
        mma_gemm_attn<<<gg, 256>>>(Ah, Al, pWh + woff[l], pWl + woff[l],
                                   ph, N_NODES, Kin, asr[l], ads[l]);
        csr_attn_agg_kernel<<<(N_NODES + 7) / 8, 256>>>(ph, bl[l], px);
        pool_max_kernel<<<(N_NODES + 63) / 64, HF>>>(px, batch, HF, FDIM + l * HF);
    }

    // g [64,832] -> latent [64,512] -> mu / log_var [64,512]
    dim3 gl((NGR + 15) / 16, LATD / 64);
    sgemm_tn<16, 64, 16, 2, 4, 128><<<gl, 128>>>(pg,   aggW, aggb, plat, NGR, LATD, GCOLS);
    sgemm_tn<16, 64, 16, 2, 4, 128><<<gl, 128>>>(plat, muW,  mub,  out,              NGR, LATD, LATD);
    sgemm_tn<16, 64, 16, 2, 4, 128><<<gl, 128>>>(plat, varW, varb, out + NGR * LATD, NGR, LATD, LATD);
}